// round 6
// baseline (speedup 1.0000x reference)
#include <cuda_runtime.h>

#define EPS 1e-5f
#define NB 512
#define NF 300
#define NP 361      // 19*19 positions
#define WP 20       // row stride in floats (80B, 16B-aligned)

typedef unsigned long long ull;

// ---------------- static device scratch (no allocation allowed) ----------------
__device__ float g_Wcomb[288 * 256];        // layer-1 combined: 256 NDI + 16 (-wr) + 16 (+wc)
__device__ float g_w2t[256 * 128];          // w2 transposed [c][o]
__device__ float g_w3t[128 * 64];           // w3 transposed [c][o]
__device__ float g_w4t[64 * 4];             // w4 transposed [c][o]
__device__ float g_gbuf[(size_t)NB * NP * 128];
__device__ float g_mbuf[NB * NP * 4];

// ---------------- f32x2 packed helpers ----------------
__device__ __forceinline__ void ffma2(ull& d, ull a, ull b) {
    asm("fma.rn.f32x2 %0, %1, %2, %0;" : "+l"(d) : "l"(a), "l"(b));
}
__device__ __forceinline__ ull dup2(float v) {
    ull r; asm("mov.b64 %0, {%1, %1};" : "=l"(r) : "f"(v)); return r;
}
__device__ __forceinline__ void unpack2(ull p, float& lo, float& hi) {
    asm("mov.b64 {%0, %1}, %2;" : "=f"(lo), "=f"(hi) : "l"(p));
}
__device__ __forceinline__ float leaky(float v) { return v >= 0.f ? v : 0.01f * v; }
__device__ __forceinline__ float relu(float v)  { return v > 0.f ? v : 0.f; }

// Load 5 packed pairs = 10 consecutive floats at row + (WX?10:0). WP=20 rows are 16B aligned.
template<int WX>
__device__ __forceinline__ void load5(const float* row, ull& p0, ull& p1, ull& p2, ull& p3, ull& p4) {
    if (WX == 0) {
        ulonglong2 A = *(const ulonglong2*)(row);      // 0..3   (16B @ 0)
        ulonglong2 B = *(const ulonglong2*)(row + 4);  // 4..7   (16B @ 16)
        ull        C = *(const ull*)(row + 8);         // 8..9   (8B  @ 32)
        p0 = A.x; p1 = A.y; p2 = B.x; p3 = B.y; p4 = C;
    } else {
        ull        A = *(const ull*)(row);             // 10..11 (8B  @ 40)
        ulonglong2 B = *(const ulonglong2*)(row + 2);  // 12..15 (16B @ 48)
        ulonglong2 C = *(const ulonglong2*)(row + 6);  // 16..19 (16B @ 64)
        p0 = A; p1 = B.x; p2 = B.y; p3 = C.x; p4 = C.y;
    }
}

// ---------------- per-chunk compute bodies ----------------
// layer-1 chunk: 32 k-rows, 2 outputs x 10 w
template<int WX>
__device__ __forceinline__ void l1_chunk(ull a0[5], ull a1[5], const float* nb, const float* wb) {
    #pragma unroll 4
    for (int r = 0; r < 32; ++r) {
        ull p0, p1, p2, p3, p4;
        load5<WX>(nb + r * WP, p0, p1, p2, p3, p4);
        float2 wv = *(const float2*)(wb + r * 256);
        ull d0 = dup2(wv.x), d1 = dup2(wv.y);
        ffma2(a0[0], p0, d0); ffma2(a0[1], p1, d0); ffma2(a0[2], p2, d0); ffma2(a0[3], p3, d0); ffma2(a0[4], p4, d0);
        ffma2(a1[0], p0, d1); ffma2(a1[1], p1, d1); ffma2(a1[2], p2, d1); ffma2(a1[3], p3, d1); ffma2(a1[4], p4, d1);
    }
}
// layer-2 chunk: 64 k-rows, 1 output x 10 w
template<int WX>
__device__ __forceinline__ void l2_chunk(ull a[5], const float* nb, const float* wb) {
    #pragma unroll 4
    for (int r = 0; r < 64; ++r) {
        ull p0, p1, p2, p3, p4;
        load5<WX>(nb + r * WP, p0, p1, p2, p3, p4);
        ull d0 = dup2(wb[r * 128]);
        ffma2(a[0], p0, d0); ffma2(a[1], p1, d0); ffma2(a[2], p2, d0); ffma2(a[3], p3, d0); ffma2(a[4], p4, d0);
    }
}
// layer-3: 128 k-rows, 1 output x 10 w
template<int WX>
__device__ __forceinline__ void l3_all(ull a[5], const float* nb, const float* wb) {
    #pragma unroll 4
    for (int k = 0; k < 128; ++k) {
        ull p0, p1, p2, p3, p4;
        load5<WX>(nb + k * WP, p0, p1, p2, p3, p4);
        ull d0 = dup2(wb[k * 64]);
        ffma2(a[0], p0, d0); ffma2(a[1], p1, d0); ffma2(a[2], p2, d0); ffma2(a[3], p3, d0); ffma2(a[4], p4, d0);
    }
}

// ---------------- prep kernel: weight repack ----------------
__global__ void prep_kernel(const float* __restrict__ w1, const float* __restrict__ w2,
                            const float* __restrict__ w3, const float* __restrict__ w4) {
    int idx = blockIdx.x * blockDim.x + threadIdx.x;
    int stride = gridDim.x * blockDim.x;
    for (int t = idx; t < 288 * 256; t += stride) {
        int k = t >> 8, o = t & 255;
        float v;
        if (k < 256) {
            int i = k >> 4, j = k & 15;
            v = w1[o * 512 + i * 32 + j * 2 + 1];
        } else if (k < 272) {
            int i = k - 256;
            float s = 0.f;
            #pragma unroll
            for (int j = 0; j < 16; j++) s += w1[o * 512 + i * 32 + j * 2];
            v = -s;
        } else {
            int j = k - 272;
            float s = 0.f;
            #pragma unroll
            for (int i = 0; i < 16; i++) s += w1[o * 512 + i * 32 + j * 2];
            v = s;
        }
        g_Wcomb[k * 256 + o] = v;
    }
    for (int t = idx; t < 256 * 128; t += stride) {
        int k = t >> 7, o = t & 127;
        g_w2t[t] = w2[o * 256 + k];
    }
    for (int t = idx; t < 128 * 64; t += stride) {
        int k = t >> 6, o = t & 63;
        g_w3t[t] = w3[o * 128 + k];
    }
    for (int t = idx; t < 256; t += stride) {
        int c = t >> 2, oh = t & 3;
        g_w4t[t] = w4[oh * 64 + c];
    }
}

// ---------------- main fused kernel: 512 threads, one block per (b, h-pair) ----------------
__global__ __launch_bounds__(512, 1) void mlp_kernel(const float* __restrict__ x,
                                                     const float* __restrict__ b1,
                                                     const float* __restrict__ b2,
                                                     const float* __restrict__ b3,
                                                     const float* __restrict__ b4) {
    extern __shared__ float sm[];
    float* s_xp = sm;                 // 320 (later reused for w4t, 256)
    float* s_N  = sm + 320;           // 2 * 288 * 20 = 11520
    float* s_h1 = s_N + 11520;        // 2 * 256 * 20 = 10240
    float* s_h2 = s_h1 + 10240;       // 2 * 128 * 20 = 5120
    float* s_wb = s_h2 + 5120;        // 2 * 8192 weight staging (double buffer)
    // s_m3 aliases s_N (dead after layer 1): 2 * 64*20

    const int b  = blockIdx.x;
    const int h0 = blockIdx.y * 2;
    const int tid = threadIdx.x;

    // ---- prefetch W1 chunk 0 early (16 floats/thread via 4 float4) ----
    float4 pf0, pf1, pf2, pf3;
    {
        const float4* src = (const float4*)g_Wcomb;
        pf0 = src[tid]; pf1 = src[tid + 512]; pf2 = src[tid + 1024]; pf3 = src[tid + 1536];
    }

    // ---- padded input row ----
    for (int i = tid; i < 320; i += 512) {
        float v = 0.f;
        if (i >= 2 && i < 302) v = x[b * NF + i - 2];
        s_xp[i] = v;
    }
    __syncthreads();

    // ---- build N for both hh ----
    for (int e = tid; e < 11520; e += 512) {
        int hh = (e >= 5760);
        int idx = e - hh * 5760;
        int k = idx / WP, w = idx - k * WP;
        int h = h0 + hh;                     // h may be 19 -> reads land in zero pad (harmless)
        float val;
        if (k < 256) {
            int i = k >> 4, j = k & 15;
            float u = s_xp[i * 19 + h];
            float v = s_xp[j * 19 + w];
            val = __fdividef(v - u, u + v + EPS);
        } else if (k < 272) {
            val = s_xp[(k - 256) * 19 + h];
        } else {
            val = s_xp[(k - 272) * 19 + w];
        }
        s_N[e] = val;
    }
    // stage W1 chunk 0 into buf0
    {
        float4* dst = (float4*)s_wb;
        dst[tid] = pf0; dst[tid + 512] = pf1; dst[tid + 1024] = pf2; dst[tid + 1536] = pf3;
    }
    __syncthreads();

    // ---- thread tiling: hh (h within pair), wx (w half), og (output group) ----
    const int hh = tid >> 8;            // 0/1
    const int t  = tid & 255;
    const int wx = t >> 7;              // 0/1 -> w0 = 0/10
    const int w0 = wx * 10;
    const int og = t & 127;
    const int hvalid = (h0 + hh) < 19;

    // ================= layer 1: 288 -> 256 (2o x 10w per thread, 512 threads) =================
    {
        const int o0 = og * 2;
        const float* myN = s_N + hh * 5760 + w0;
        ull a0[5], a1[5];
        {
            float2 bb = *(const float2*)(b1 + o0);
            ull i0 = dup2(bb.x), i1 = dup2(bb.y);
            #pragma unroll
            for (int i = 0; i < 5; i++) { a0[i] = i0; a1[i] = i1; }
        }
        for (int c = 0; c < 9; ++c) {
            // prefetch next chunk (or L2 chunk 0 on the last iter)
            float4 q0, q1, q2, q3;
            {
                const float4* s4 = (c < 8) ? (const float4*)(g_Wcomb + (c + 1) * 8192)
                                           : (const float4*)g_w2t;
                q0 = s4[tid]; q1 = s4[tid + 512]; q2 = s4[tid + 1024]; q3 = s4[tid + 1536];
            }
            const float* wb = s_wb + (c & 1) * 8192 + o0;
            const float* nb = myN + c * 32 * WP;
            if (wx == 0) l1_chunk<0>(a0, a1, nb, wb);
            else         l1_chunk<1>(a0, a1, nb, wb);
            {
                float4* dd = (float4*)(s_wb + ((c + 1) & 1) * 8192);
                dd[tid] = q0; dd[tid + 512] = q1; dd[tid + 1024] = q2; dd[tid + 1536] = q3;
            }
            __syncthreads();
        }
        // epilogue: leaky -> s_h1
        float* myH1 = s_h1 + hh * 5120 + w0;
        float* dst0 = myH1 + o0 * WP;
        float* dst1 = dst0 + WP;
        #pragma unroll
        for (int i = 0; i < 5; ++i) {
            float lo, hi;
            unpack2(a0[i], lo, hi); dst0[2 * i] = leaky(lo); dst0[2 * i + 1] = leaky(hi);
            unpack2(a1[i], lo, hi); dst1[2 * i] = leaky(lo); dst1[2 * i + 1] = leaky(hi);
        }
    }
    __syncthreads();

    // ================= layer 2: 256 -> 128 (1o x 10w per thread, 512 threads) =================
    {
        const int o0 = og;              // 128 outputs
        const float* myH1 = s_h1 + hh * 5120 + w0;
        ull acc[5];
        {
            ull i0 = dup2(b2[o0]);
            #pragma unroll
            for (int i = 0; i < 5; i++) acc[i] = i0;
        }
        // L1 loop left w2t chunk0 in buf[1]; read buf (c&1)^1, write buf (c&1)
        for (int c = 0; c < 4; ++c) {
            float4 q0, q1, q2, q3;
            bool pf = (c < 3);
            if (pf) {
                const float4* s4 = (const float4*)(g_w2t + (c + 1) * 8192);
                q0 = s4[tid]; q1 = s4[tid + 512]; q2 = s4[tid + 1024]; q3 = s4[tid + 1536];
            }
            const float* wb = s_wb + ((c & 1) ^ 1) * 8192 + o0;
            const float* nb = myH1 + c * 64 * WP;
            if (wx == 0) l2_chunk<0>(acc, nb, wb);
            else         l2_chunk<1>(acc, nb, wb);
            if (pf) {
                float4* dd = (float4*)(s_wb + (c & 1) * 8192);
                dd[tid] = q0; dd[tid + 512] = q1; dd[tid + 1024] = q2; dd[tid + 1536] = q3;
            }
            __syncthreads();
        }
        // epilogue: leaky -> s_h2 and g_gbuf
        float v[10];
        #pragma unroll
        for (int i = 0; i < 5; ++i) {
            float lo, hi;
            unpack2(acc[i], lo, hi); v[2 * i] = leaky(lo); v[2 * i + 1] = leaky(hi);
        }
        float* d0 = s_h2 + hh * 2560 + o0 * WP + w0;
        #pragma unroll
        for (int i = 0; i < 10; ++i) d0[i] = v[i];
        if (hvalid) {
            const size_t posbase = (size_t)(b * NP + (h0 + hh) * 19);
            #pragma unroll
            for (int i = 0; i < 10; ++i) {
                int w = w0 + i;
                if (w < 19) g_gbuf[(posbase + w) * 128 + o0] = v[i];
            }
        }
        // stage whole w3t (8192 floats) into buf0 + w4t (256) into s_xp
        {
            const float4* s4 = (const float4*)g_w3t;
            float4* d4 = (float4*)s_wb;
            #pragma unroll
            for (int q = 0; q < 4; ++q) d4[tid + q * 512] = s4[tid + q * 512];
            if (tid < 256) s_xp[tid] = g_w4t[tid];
        }
    }
    __syncthreads();

    // ================= layer 3: 128 -> 64 (1o x 10w, 256 threads) =================
    if (tid < 256) {
        const int hh3 = tid >> 7, t3 = tid & 127;
        const int wx3 = t3 >> 6, w30 = wx3 * 10;
        const int o0 = t3 & 63;
        const float* myH2 = s_h2 + hh3 * 2560 + w30;
        ull acc[5];
        {
            ull i0 = dup2(b3[o0]);
            #pragma unroll
            for (int i = 0; i < 5; i++) acc[i] = i0;
        }
        if (wx3 == 0) l3_all<0>(acc, myH2, s_wb + o0);
        else          l3_all<1>(acc, myH2, s_wb + o0);
        float* m3 = s_N + hh3 * 1280;   // alias: s_N dead
        float* d0 = m3 + o0 * WP + w30;
        #pragma unroll
        for (int i = 0; i < 5; ++i) {
            float lo, hi;
            unpack2(acc[i], lo, hi); d0[2 * i] = relu(lo); d0[2 * i + 1] = relu(hi);
        }
    }
    __syncthreads();

    // ================= layer 4: 64 -> 4, logits =================
    if (tid < 152) {
        const int hh4 = (tid >= 76);
        const int tt = tid - hh4 * 76;
        const int w = tt >> 2, oh = tt & 3;
        const int h = h0 + hh4;
        const float* m3 = s_N + hh4 * 1280;
        float acc = b4[oh];
        #pragma unroll 8
        for (int c = 0; c < 64; ++c) acc += m3[c * WP + w] * s_xp[c * 4 + oh];
        if (h < 19) g_mbuf[(b * NP + h * 19 + w) * 4 + oh] = relu(acc);
    }
}

// ---------------- softmax over 361 positions + weighted reduction ----------------
__global__ __launch_bounds__(128) void softmax_kernel(float* __restrict__ out) {
    __shared__ float s_m[NP * 4];
    __shared__ float s_w[NP * 4];
    __shared__ float s_mx[4];
    __shared__ float s_iz[4];
    const int b = blockIdx.x;
    const int tid = threadIdx.x;

    for (int i = tid; i < NP * 4; i += 128) s_m[i] = g_mbuf[b * NP * 4 + i];
    __syncthreads();
    if (tid < 4) {
        float mx = -1e30f;
        for (int p = 0; p < NP; p++) mx = fmaxf(mx, s_m[p * 4 + tid]);
        s_mx[tid] = mx;
    }
    __syncthreads();
    for (int i = tid; i < NP * 4; i += 128) s_w[i] = __expf(s_m[i] - s_mx[i & 3]);
    __syncthreads();
    if (tid < 4) {
        float z = 0.f;
        for (int p = 0; p < NP; p++) z += s_w[p * 4 + tid];
        s_iz[tid] = __fdividef(1.f, z);
    }
    __syncthreads();
    const int head = tid >> 5;
    const float* gp = g_gbuf + (size_t)b * NP * 128 + tid;
    float acc = 0.f;
    #pragma unroll 4
    for (int p = 0; p < NP; p++) acc += s_w[p * 4 + head] * gp[(size_t)p * 128];
    out[b * 128 + tid] = acc * s_iz[head];
}

// ---------------- launch ----------------
extern "C" void kernel_launch(void* const* d_in, const int* in_sizes, int n_in,
                              void* d_out, int out_size) {
    const float* x  = (const float*)d_in[0];
    const float* w1 = (const float*)d_in[1];
    const float* b1 = (const float*)d_in[2];
    const float* w2 = (const float*)d_in[3];
    const float* b2 = (const float*)d_in[4];
    const float* w3 = (const float*)d_in[5];
    const float* b3 = (const float*)d_in[6];
    const float* w4 = (const float*)d_in[7];
    const float* b4 = (const float*)d_in[8];
    float* out = (float*)d_out;

    const int smem_bytes = (320 + 11520 + 10240 + 5120 + 16384) * sizeof(float); // 174336
    cudaFuncSetAttribute(mlp_kernel, cudaFuncAttributeMaxDynamicSharedMemorySize, smem_bytes);

    prep_kernel<<<128, 256>>>(w1, w2, w3, w4);
    mlp_kernel<<<dim3(NB, 10), 512, smem_bytes>>>(x, b1, b2, b3, b4);
    softmax_kernel<<<NB, 128>>>(out);
}

// round 7
// speedup vs baseline: 1.7106x; 1.7106x over previous
#include <cuda_runtime.h>
#include <cuda_bf16.h>
#include <cstdint>

#define EPS 1e-5f
#define NB 512
#define NF 300
#define NP 361
#define AP 296                    // A-plane k-stride (bf16 elems)
#define WS 264                    // W-stage n-stride (bf16 elems)
#define A_PLANE_B (128 * AP * 2)  // 75776 bytes
#define W_PLANE_B (16 * WS * 2)   // 8448 bytes
#define W_BUF_B   (2 * W_PLANE_B) // 16896 bytes (hi+lo planes)
#define SMEM_TOTAL (4224 + 2 * A_PLANE_B + 2 * W_BUF_B) // 189568

// ---------------- static device scratch ----------------
__device__ __align__(16) __nv_bfloat16 g_W1h[288 * 256], g_W1l[288 * 256];
__device__ __align__(16) __nv_bfloat16 g_W2h[256 * 128], g_W2l[256 * 128];
__device__ __align__(16) __nv_bfloat16 g_W3h[128 * 64],  g_W3l[128 * 64];
__device__ float g_w4t[256];
__device__ float g_gbuf[(size_t)NB * NP * 128];
__device__ float g_mbuf[NB * NP * 4];

// ---------------- ptx helpers ----------------
__device__ __forceinline__ uint32_t cvta_s(const void* p) {
    uint32_t a; asm("{.reg .u64 t; cvta.to.shared.u64 t,%1; cvt.u32.u64 %0,t;}" : "=r"(a) : "l"(p)); return a;
}
__device__ __forceinline__ void ldmA(uint32_t a, uint32_t r[4]) {
    asm volatile("ldmatrix.sync.aligned.m8n8.x4.shared.b16 {%0,%1,%2,%3},[%4];"
                 : "=r"(r[0]), "=r"(r[1]), "=r"(r[2]), "=r"(r[3]) : "r"(a));
}
__device__ __forceinline__ void ldmBT(uint32_t a, uint32_t r[4]) {
    asm volatile("ldmatrix.sync.aligned.m8n8.x4.trans.shared.b16 {%0,%1,%2,%3},[%4];"
                 : "=r"(r[0]), "=r"(r[1]), "=r"(r[2]), "=r"(r[3]) : "r"(a));
}
__device__ __forceinline__ void mma(float c[4], const uint32_t a[4], uint32_t b0, uint32_t b1) {
    asm volatile("mma.sync.aligned.m16n8k16.row.col.f32.bf16.bf16.f32 "
                 "{%0,%1,%2,%3},{%4,%5,%6,%7},{%8,%9},{%0,%1,%2,%3};"
                 : "+f"(c[0]), "+f"(c[1]), "+f"(c[2]), "+f"(c[3])
                 : "r"(a[0]), "r"(a[1]), "r"(a[2]), "r"(a[3]), "r"(b0), "r"(b1));
}
__device__ __forceinline__ void cpa16(uint32_t d, const void* s) {
    asm volatile("cp.async.ca.shared.global [%0],[%1],16;" :: "r"(d), "l"(s));
}
#define CP_COMMIT asm volatile("cp.async.commit_group;")
#define CP_WAIT1  asm volatile("cp.async.wait_group 1;")
#define CP_WAIT0  asm volatile("cp.async.wait_group 0;")

__device__ __forceinline__ float leaky(float v) { return v >= 0.f ? v : 0.01f * v; }
__device__ __forceinline__ float relu(float v)  { return v > 0.f ? v : 0.f; }
__device__ __forceinline__ void split2(float v0, float v1, uint32_t& hp, uint32_t& lp) {
    __nv_bfloat162 h = __floats2bfloat162_rn(v0, v1);
    float h0 = __bfloat162float(__low2bfloat16(h)), h1 = __bfloat162float(__high2bfloat16(h));
    __nv_bfloat162 l = __floats2bfloat162_rn(v0 - h0, v1 - h1);
    hp = *(uint32_t*)&h; lp = *(uint32_t*)&l;
}

// stage one k16 chunk (hi+lo planes) of an [K][N] bf16 weight matrix into smem buffer
template<int N>
__device__ __forceinline__ void stage(const __nv_bfloat16* gh, const __nv_bfloat16* gl,
                                      int kc, uint32_t wbuf) {
    constexpr int UNITS = 2 * N;  // 16 rows * N/8 16B-units per plane
    for (int u = threadIdx.x; u < 2 * UNITS; u += 512) {
        int pl = u / UNITS, w = u - pl * UNITS;
        int r = w / (N / 8), s = w - r * (N / 8);
        const __nv_bfloat16* src = (pl ? gl : gh) + (kc * 16 + r) * N + s * 8;
        cpa16(wbuf + pl * W_PLANE_B + (r * WS + s * 8) * 2, src);
    }
}

// generic 3-term-split GEMM: A planes (128 x K) in smem, W staged from global.
// caller must have staged+committed chunk 0 into buffer 0.
template<int NSTEPS, int NF2, int N>
__device__ __forceinline__ void gemm_ts(uint32_t aHi, uint32_t aLo, uint32_t wst,
                                        const __nv_bfloat16* gh, const __nv_bfloat16* gl,
                                        float (&acc)[2][NF2 * 2][4], int wm, int wn) {
    const int lane = threadIdx.x & 31;
    const uint32_t aoff0 = (uint32_t)(((wm * 32 + (lane & 15)) * AP + (lane >> 4) * 8) * 2);
    const int bg = lane >> 3, bi = lane & 7;
    const uint32_t boff = (uint32_t)((((bg & 1) * 8 + bi) * WS + (bg >> 1) * 8) * 2);
    for (int c = 0; c < NSTEPS; c++) {
        if (c + 1 < NSTEPS) { stage<N>(gh, gl, c + 1, wst + ((c + 1) & 1) * W_BUF_B); CP_COMMIT; CP_WAIT1; }
        else { CP_WAIT0; }
        __syncthreads();
        const uint32_t wb = wst + (c & 1) * W_BUF_B + boff;
        uint32_t ah[2][4], al[2][4];
        const uint32_t ab = aoff0 + c * 32;
        ldmA(aHi + ab, ah[0]); ldmA(aHi + ab + 16 * AP * 2, ah[1]);
        ldmA(aLo + ab, al[0]); ldmA(aLo + ab + 16 * AP * 2, al[1]);
        #pragma unroll
        for (int ng = 0; ng < NF2; ng++) {
            const uint32_t nb = (uint32_t)((wn * (NF2 * 16) + ng * 16) * 2);
            uint32_t bh[4], bl[4];
            ldmBT(wb + nb, bh);
            ldmBT(wb + nb + W_PLANE_B, bl);
            #pragma unroll
            for (int mf = 0; mf < 2; mf++) {
                mma(acc[mf][ng * 2 + 0], ah[mf], bh[0], bh[1]);
                mma(acc[mf][ng * 2 + 0], al[mf], bh[0], bh[1]);
                mma(acc[mf][ng * 2 + 0], ah[mf], bl[0], bl[1]);
                mma(acc[mf][ng * 2 + 1], ah[mf], bh[2], bh[3]);
                mma(acc[mf][ng * 2 + 1], al[mf], bh[2], bh[3]);
                mma(acc[mf][ng * 2 + 1], ah[mf], bl[2], bl[3]);
            }
        }
        __syncthreads();
    }
}

// ---------------- prep: weight repack + bf16 hi/lo split ----------------
__global__ void prep_kernel(const float* __restrict__ w1, const float* __restrict__ w2,
                            const float* __restrict__ w3, const float* __restrict__ w4) {
    int idx = blockIdx.x * blockDim.x + threadIdx.x;
    int stride = gridDim.x * blockDim.x;
    // W1comb[k][o]: k<256 NDI weight (i=k>>4,j=k&15); 256..271: -wr[i]; 272..287: +wc[j]
    for (int t = idx; t < 288 * 256; t += stride) {
        int k = t >> 8, o = t & 255;
        float v;
        if (k < 256) {
            int i = k >> 4, j = k & 15;
            v = w1[o * 512 + i * 32 + j * 2 + 1];
        } else if (k < 272) {
            int i = k - 256; float s = 0.f;
            #pragma unroll
            for (int j = 0; j < 16; j++) s += w1[o * 512 + i * 32 + j * 2];
            v = -s;
        } else {
            int j = k - 272; float s = 0.f;
            #pragma unroll
            for (int i = 0; i < 16; i++) s += w1[o * 512 + i * 32 + j * 2];
            v = s;
        }
        __nv_bfloat16 h = __float2bfloat16(v);
        g_W1h[t] = h; g_W1l[t] = __float2bfloat16(v - __bfloat162float(h));
    }
    for (int t = idx; t < 256 * 128; t += stride) {
        int k = t >> 7, o = t & 127;
        float v = w2[o * 256 + k];
        __nv_bfloat16 h = __float2bfloat16(v);
        g_W2h[t] = h; g_W2l[t] = __float2bfloat16(v - __bfloat162float(h));
    }
    for (int t = idx; t < 128 * 64; t += stride) {
        int k = t >> 6, o = t & 63;
        float v = w3[o * 128 + k];
        __nv_bfloat16 h = __float2bfloat16(v);
        g_W3h[t] = h; g_W3l[t] = __float2bfloat16(v - __bfloat162float(h));
    }
    for (int t = idx; t < 256; t += stride) g_w4t[t] = w4[(t & 3) * 64 + (t >> 2)];
}

// ---------------- main fused tensor kernel: one CTA per (batch, 128-row tile) ----------------
__global__ __launch_bounds__(512, 1) void mlp_kernel(const float* __restrict__ x,
                                                     const float* __restrict__ b1,
                                                     const float* __restrict__ b2,
                                                     const float* __restrict__ b3,
                                                     const float* __restrict__ b4) {
    extern __shared__ char smem[];
    float* s_xp = (float*)smem;       // 320
    float* s_b1 = s_xp + 320;         // 256
    float* s_b2 = s_b1 + 256;         // 128
    float* s_b3 = s_b2 + 128;         // 64
    float* s_b4 = s_b3 + 64;          // 8
    float* s_w4 = s_b4 + 8;           // 256  (ends at 4128B; planes at 4224)
    __nv_bfloat16* s_Ahi = (__nv_bfloat16*)(smem + 4224);
    __nv_bfloat16* s_Alo = (__nv_bfloat16*)(smem + 4224 + A_PLANE_B);
    char* s_w = smem + 4224 + 2 * A_PLANE_B;     // 33792B staging; later h3 fp32 [128][66]
    float* s_h3 = (float*)s_w;

    const int b = blockIdx.x;
    const int pos0 = blockIdx.y * 128;
    const int tid = threadIdx.x;
    const int lane = tid & 31, ww = tid >> 5;
    const int wm = ww >> 2, wn = ww & 3;

    const uint32_t aHi = cvta_s(s_Ahi), aLo = cvta_s(s_Alo), wst = cvta_s(s_w);

    // preload xp, biases, w4
    for (int i = tid; i < 320; i += 512) {
        float v = 0.f;
        if (i >= 2 && i < 302) v = x[b * NF + i - 2];
        s_xp[i] = v;
    }
    if (tid < 256) { s_b1[tid] = b1[tid]; s_w4[tid] = g_w4t[tid]; }
    if (tid < 128) s_b2[tid] = b2[tid];
    if (tid < 64)  s_b3[tid] = b3[tid];
    if (tid < 4)   s_b4[tid] = b4[tid];

    // stage W1 chunk 0 early (overlaps with A build)
    stage<256>(g_W1h, g_W1l, 0, wst); CP_COMMIT;
    __syncthreads();

    // ---- build A (layer-1 features), bf16 hi/lo planes [128][288] ----
    for (int e = tid; e < 128 * 288; e += 512) {
        int m = e / 288, k = e - m * 288;
        int p = pos0 + m;
        int h = p / 19, w = p - h * 19;
        float val = 0.f;
        if (p < NP) {
            if (k < 256) {
                int i = k >> 4, j = k & 15;
                float u = s_xp[i * 19 + h];
                float v = s_xp[j * 19 + w];
                val = __fdividef(v - u, u + v + EPS);
            } else if (k < 272) {
                val = s_xp[(k - 256) * 19 + h];
            } else {
                val = s_xp[(k - 272) * 19 + w];
            }
        }
        __nv_bfloat16 hb = __float2bfloat16(val);
        s_Ahi[m * AP + k] = hb;
        s_Alo[m * AP + k] = __float2bfloat16(val - __bfloat162float(hb));
    }
    // (gemm's first internal __syncthreads orders A-plane writes before reads)

    const int r0 = lane >> 2, c0 = (lane & 3) * 2;

    // ================= layer 1: K=288 -> N=256 =================
    {
        float a1[2][8][4];
        #pragma unroll
        for (int i = 0; i < 2; i++)
            #pragma unroll
            for (int j = 0; j < 8; j++)
                { a1[i][j][0] = a1[i][j][1] = a1[i][j][2] = a1[i][j][3] = 0.f; }
        gemm_ts<18, 4, 256>(aHi, aLo, wst, g_W1h, g_W1l, a1, wm, wn);
        // epilogue: +bias, leaky, split -> A planes (h1, K=256)
        #pragma unroll
        for (int mf = 0; mf < 2; mf++) {
            int mm = wm * 32 + mf * 16 + r0;
            #pragma unroll
            for (int nf = 0; nf < 8; nf++) {
                int nn = wn * 64 + nf * 8 + c0;
                float bb0 = s_b1[nn], bb1 = s_b1[nn + 1];
                uint32_t hp, lp;
                split2(leaky(a1[mf][nf][0] + bb0), leaky(a1[mf][nf][1] + bb1), hp, lp);
                *(uint32_t*)(s_Ahi + mm * AP + nn) = hp;
                *(uint32_t*)(s_Alo + mm * AP + nn) = lp;
                split2(leaky(a1[mf][nf][2] + bb0), leaky(a1[mf][nf][3] + bb1), hp, lp);
                *(uint32_t*)(s_Ahi + (mm + 8) * AP + nn) = hp;
                *(uint32_t*)(s_Alo + (mm + 8) * AP + nn) = lp;
            }
        }
    }
    stage<128>(g_W2h, g_W2l, 0, wst); CP_COMMIT;

    // ================= layer 2: K=256 -> N=128 =================
    {
        float a2[2][4][4];
        #pragma unroll
        for (int i = 0; i < 2; i++)
            #pragma unroll
            for (int j = 0; j < 4; j++)
                { a2[i][j][0] = a2[i][j][1] = a2[i][j][2] = a2[i][j][3] = 0.f; }
        gemm_ts<16, 2, 128>(aHi, aLo, wst, g_W2h, g_W2l, a2, wm, wn);
        // epilogue: leaky -> gbuf fp32 + A planes (h2, K=128)
        #pragma unroll
        for (int mf = 0; mf < 2; mf++) {
            #pragma unroll
            for (int nf = 0; nf < 4; nf++) {
                int nn = wn * 32 + nf * 8 + c0;
                float bb0 = s_b2[nn], bb1 = s_b2[nn + 1];
                #pragma unroll
                for (int half = 0; half < 2; half++) {
                    int mm = wm * 32 + mf * 16 + r0 + half * 8;
                    float v0 = leaky(a2[mf][nf][half * 2 + 0] + bb0);
                    float v1 = leaky(a2[mf][nf][half * 2 + 1] + bb1);
                    uint32_t hp, lp;
                    split2(v0, v1, hp, lp);
                    *(uint32_t*)(s_Ahi + mm * AP + nn) = hp;
                    *(uint32_t*)(s_Alo + mm * AP + nn) = lp;
                    int p = pos0 + mm;
                    if (p < NP)
                        *(float2*)(g_gbuf + ((size_t)b * NP + p) * 128 + nn) = make_float2(v0, v1);
                }
            }
        }
    }
    stage<64>(g_W3h, g_W3l, 0, wst); CP_COMMIT;

    // ================= layer 3: K=128 -> N=64 =================
    {
        float a3[2][2][4];
        #pragma unroll
        for (int i = 0; i < 2; i++)
            #pragma unroll
            for (int j = 0; j < 2; j++)
                { a3[i][j][0] = a3[i][j][1] = a3[i][j][2] = a3[i][j][3] = 0.f; }
        gemm_ts<8, 1, 64>(aHi, aLo, wst, g_W3h, g_W3l, a3, wm, wn);
        // epilogue: relu -> s_h3 fp32 [128][66]
        #pragma unroll
        for (int mf = 0; mf < 2; mf++) {
            #pragma unroll
            for (int nf = 0; nf < 2; nf++) {
                int nn = wn * 16 + nf * 8 + c0;
                float bb0 = s_b3[nn], bb1 = s_b3[nn + 1];
                #pragma unroll
                for (int half = 0; half < 2; half++) {
                    int mm = wm * 32 + mf * 16 + r0 + half * 8;
                    float v0 = relu(a3[mf][nf][half * 2 + 0] + bb0);
                    float v1 = relu(a3[mf][nf][half * 2 + 1] + bb1);
                    *(float2*)(s_h3 + mm * 66 + nn) = make_float2(v0, v1);
                }
            }
        }
    }
    __syncthreads();

    // ================= layer 4: 64 -> 4, logits =================
    {
        int m = tid >> 2, oh = tid & 3;
        int p = pos0 + m;
        float acc = s_b4[oh];
        #pragma unroll 8
        for (int c = 0; c < 64; c++) acc += s_h3[m * 66 + c] * s_w4[c * 4 + oh];
        if (p < NP) g_mbuf[((size_t)b * NP + p) * 4 + oh] = relu(acc);
    }
}

// ---------------- softmax over 361 positions + weighted reduction ----------------
__global__ __launch_bounds__(128) void softmax_kernel(float* __restrict__ out) {
    __shared__ float s_m[NP * 4];
    __shared__ float s_w[NP * 4];
    __shared__ float s_mx[4];
    __shared__ float s_iz[4];
    const int b = blockIdx.x;
    const int tid = threadIdx.x;

    for (int i = tid; i < NP * 4; i += 128) s_m[i] = g_mbuf[b * NP * 4 + i];
    __syncthreads();
    if (tid < 4) {
        float mx = -1e30f;
        for (int p = 0; p < NP; p++) mx = fmaxf(mx, s_m[p * 4 + tid]);
        s_mx[tid] = mx;
    }
    __syncthreads();
    for (int i = tid; i < NP * 4; i += 128) s_w[i] = __expf(s_m[i] - s_mx[i & 3]);
    __syncthreads();
    if (tid < 4) {
        float z = 0.f;
        for (int p = 0; p < NP; p++) z += s_w[p * 4 + tid];
        s_iz[tid] = __fdividef(1.f, z);
    }
    __syncthreads();
    const int head = tid >> 5;
    const float* gp = g_gbuf + (size_t)b * NP * 128 + tid;
    float acc = 0.f;
    #pragma unroll 4
    for (int p = 0; p < NP; p++) acc += s_w[p * 4 + head] * gp[(size_t)p * 128];
    out[b * 128 + tid] = acc * s_iz[head];
}

// ---------------- launch ----------------
extern "C" void kernel_launch(void* const* d_in, const int* in_sizes, int n_in,
                              void* d_out, int out_size) {
    const float* x  = (const float*)d_in[0];
    const float* w1 = (const float*)d_in[1];
    const float* b1 = (const float*)d_in[2];
    const float* w2 = (const float*)d_in[3];
    const float* b2 = (const float*)d_in[4];
    const float* w3 = (const float*)d_in[5];
    const float* b3 = (const float*)d_in[6];
    const float* w4 = (const float*)d_in[7];
    const float* b4 = (const float*)d_in[8];
    float* out = (float*)d_out;

    cudaFuncSetAttribute(mlp_kernel, cudaFuncAttributeMaxDynamicSharedMemorySize, SMEM_TOTAL);

    prep_kernel<<<128, 256>>>(w1, w2, w3, w4);
    mlp_kernel<<<dim3(NB, 3), 512, SMEM_TOTAL>>>(x, b1, b2, b3, b4);
    softmax_kernel<<<NB, 128>>>(out);
}

// round 9
// speedup vs baseline: 3.3797x; 1.9758x over previous
#include <cuda_runtime.h>
#include <cuda_fp16.h>
#include <cstdint>

#define EPS 1e-5f
#define NB 512
#define NFX 300
#define NP 361
#define AP 296              // A-plane row stride (halfs)

// per-layer staging strides (halfs) and plane sizes (bytes)
#define WS1 264
#define WS2 136
#define WS3 72
#define PL1 (32 * WS1 * 2)  // 16896
#define PL2 (32 * WS2 * 2)  // 8704
#define PL3 (32 * WS3 * 2)  // 4608

#define A_OFF 1280                       // after 320-float xp
#define W_OFF (A_OFF + 64 * AP * 2)      // 39168
#define SMEM_TOTAL (W_OFF + 2 * 2 * PL1) // 106752

// ---------------- static device scratch ----------------
__device__ __align__(16) __half g_W1h[288 * 256], g_W1l[288 * 256];  // [k][o]
__device__ __align__(16) __half g_W2h[256 * 128], g_W2l[256 * 128];
__device__ __align__(16) __half g_W3h[128 * 64],  g_W3l[128 * 64];
__device__ float g_w4t[256];
__device__ float g_gbuf[(size_t)NB * NP * 128];
__device__ float g_mbuf[NB * NP * 4];

// ---------------- helpers ----------------
__device__ __forceinline__ uint32_t cvta_s(const void* p) {
    uint32_t a; asm("{.reg .u64 t; cvta.to.shared.u64 t,%1; cvt.u32.u64 %0,t;}" : "=r"(a) : "l"(p)); return a;
}
__device__ __forceinline__ void ldmA(uint32_t a, uint32_t r[4]) {
    asm volatile("ldmatrix.sync.aligned.m8n8.x4.shared.b16 {%0,%1,%2,%3},[%4];"
                 : "=r"(r[0]), "=r"(r[1]), "=r"(r[2]), "=r"(r[3]) : "r"(a));
}
__device__ __forceinline__ void ldmBT(uint32_t a, uint32_t r[4]) {
    asm volatile("ldmatrix.sync.aligned.m8n8.x4.trans.shared.b16 {%0,%1,%2,%3},[%4];"
                 : "=r"(r[0]), "=r"(r[1]), "=r"(r[2]), "=r"(r[3]) : "r"(a));
}
__device__ __forceinline__ void mma(float c[4], const uint32_t a[4], uint32_t b0, uint32_t b1) {
    asm volatile("mma.sync.aligned.m16n8k16.row.col.f32.f16.f16.f32 "
                 "{%0,%1,%2,%3},{%4,%5,%6,%7},{%8,%9},{%0,%1,%2,%3};"
                 : "+f"(c[0]), "+f"(c[1]), "+f"(c[2]), "+f"(c[3])
                 : "r"(a[0]), "r"(a[1]), "r"(a[2]), "r"(a[3]), "r"(b0), "r"(b1));
}
__device__ __forceinline__ void cpa16(uint32_t d, const void* s) {
    asm volatile("cp.async.ca.shared.global [%0],[%1],16;" :: "r"(d), "l"(s));
}
#define CP_COMMIT asm volatile("cp.async.commit_group;")
#define CP_WAIT1  asm volatile("cp.async.wait_group 1;")
#define CP_WAIT0  asm volatile("cp.async.wait_group 0;")

__device__ __forceinline__ float leaky(float v) { return v >= 0.f ? v : 0.01f * v; }
__device__ __forceinline__ float relu(float v)  { return v > 0.f ? v : 0.f; }

// stage one k32 chunk (hi + lo planes) of a [K][N] fp16 weight matrix
template<int N, int WSN, int PL>
__device__ __forceinline__ void stageW(const __half* gh, const __half* gl,
                                       int chunk, uint32_t dst, int tid) {
    const int ROWU = N / 8;
    const int TOT = 32 * ROWU;
    for (int u = tid; u < 2 * TOT; u += 256) {
        int pl = u / TOT, w = u - pl * TOT;
        int r = w / ROWU, s = w - r * ROWU;
        const __half* src = (pl ? gl : gh) + (size_t)(chunk * 32 + r) * N + s * 8;
        cpa16(dst + pl * PL + (r * WSN + s * 8) * 2, src);
    }
}

// 2-term GEMM: D = A_h * (B_h + B_l). A: single fp16 plane [64 x K] (stride AP).
// Caller must have staged+committed chunk 0 into buffer 0.
template<int CH, int NFRG, int N, int WSN, int PL>
__device__ __forceinline__ void run_gemm(uint32_t aBase, uint32_t wst,
                                         const __half* gWh, const __half* gWl,
                                         float (&acc)[2][NFRG * 2][4],
                                         int wm, int wn, int lane, int tid) {
    const uint32_t aoff = (uint32_t)(((wm * 32 + (lane & 15)) * AP + (lane >> 4) * 8) * 2);
    const int bg = lane >> 3, bi = lane & 7;
    const uint32_t boff = (uint32_t)((((bg & 1) * 8 + bi) * WSN + (bg >> 1) * 8) * 2);
    for (int c = 0; c < CH; c++) {
        if (c + 1 < CH) {
            stageW<N, WSN, PL>(gWh, gWl, c + 1, wst + ((c + 1) & 1) * (2 * PL), tid);
            CP_COMMIT; CP_WAIT1;
        } else {
            CP_WAIT0;
        }
        __syncthreads();
        const uint32_t wb = wst + (c & 1) * (2 * PL);
        #pragma unroll
        for (int ks = 0; ks < 2; ks++) {
            uint32_t ab = aBase + aoff + (uint32_t)(c * 2 + ks) * 32;
            uint32_t a0[4], a1[4];
            ldmA(ab, a0);
            ldmA(ab + 16 * AP * 2, a1);
            const uint32_t kb = wb + boff + (uint32_t)ks * 16 * WSN * 2;
            #pragma unroll
            for (int ng = 0; ng < NFRG; ng++) {
                uint32_t nb = (uint32_t)(((wn * NFRG + ng) * 16) * 2);
                uint32_t bh[4], bl[4];
                ldmBT(kb + nb, bh);
                ldmBT(kb + nb + PL, bl);
                mma(acc[0][ng * 2 + 0], a0, bh[0], bh[1]);
                mma(acc[0][ng * 2 + 0], a0, bl[0], bl[1]);
                mma(acc[0][ng * 2 + 1], a0, bh[2], bh[3]);
                mma(acc[0][ng * 2 + 1], a0, bl[2], bl[3]);
                mma(acc[1][ng * 2 + 0], a1, bh[0], bh[1]);
                mma(acc[1][ng * 2 + 0], a1, bl[0], bl[1]);
                mma(acc[1][ng * 2 + 1], a1, bh[2], bh[3]);
                mma(acc[1][ng * 2 + 1], a1, bl[2], bl[3]);
            }
        }
        __syncthreads();
    }
}

// ---------------- prep: repack weights, fp16 hi/lo split, [k][o] layout ----------------
__global__ void prep_kernel(const float* __restrict__ w1, const float* __restrict__ w2,
                            const float* __restrict__ w3, const float* __restrict__ w4) {
    int idx = blockIdx.x * blockDim.x + threadIdx.x;
    int stride = gridDim.x * blockDim.x;
    // layer 1 combined K=288: k<256 NDI weight (i=k>>4,j=k&15); 256..271: -wr[i]; 272..287: +wc[j]
    for (int t = idx; t < 288 * 256; t += stride) {
        int k = t >> 8, o = t & 255;
        float v;
        if (k < 256) {
            int i = k >> 4, j = k & 15;
            v = w1[o * 512 + i * 32 + j * 2 + 1];
        } else if (k < 272) {
            int i = k - 256; float s = 0.f;
            #pragma unroll
            for (int j = 0; j < 16; j++) s += w1[o * 512 + i * 32 + j * 2];
            v = -s;
        } else {
            int j = k - 272; float s = 0.f;
            #pragma unroll
            for (int i = 0; i < 16; i++) s += w1[o * 512 + i * 32 + j * 2];
            v = s;
        }
        __half h = __float2half_rn(v);
        g_W1h[t] = h; g_W1l[t] = __float2half_rn(v - __half2float(h));
    }
    for (int t = idx; t < 256 * 128; t += stride) {
        int k = t >> 7, o = t & 127;
        float v = w2[o * 256 + k];
        __half h = __float2half_rn(v);
        g_W2h[t] = h; g_W2l[t] = __float2half_rn(v - __half2float(h));
    }
    for (int t = idx; t < 128 * 64; t += stride) {
        int k = t >> 6, o = t & 63;
        float v = w3[o * 128 + k];
        __half h = __float2half_rn(v);
        g_W3h[t] = h; g_W3l[t] = __float2half_rn(v - __half2float(h));
    }
    for (int t = idx; t < 256; t += stride) g_w4t[t] = w4[(t & 3) * 64 + (t >> 2)];
}

// ---------------- main fused kernel: one CTA per (batch, 64-pos tile), 2 CTA/SM ----------------
__global__ __launch_bounds__(256, 2) void mlp_kernel(const float* __restrict__ x,
                                                     const float* __restrict__ b1,
                                                     const float* __restrict__ b2,
                                                     const float* __restrict__ b3,
                                                     const float* __restrict__ b4) {
    extern __shared__ char smem[];
    float* s_xp = (float*)smem;
    __half* s_A = (__half*)(smem + A_OFF);
    float* s_h3 = (float*)(smem + W_OFF);    // reuses staging area after L3 GEMM
    const uint32_t sb = cvta_s(smem);
    const uint32_t aBase = sb + A_OFF, wst = sb + W_OFF;

    const int b = blockIdx.x, pos0 = blockIdx.y * 64, tid = threadIdx.x;
    const int lane = tid & 31, ww = tid >> 5;
    const int wm = ww >> 2, wn = ww & 3;     // 2 m-warps x 4 n-warps
    const int r0 = lane >> 2, c0 = (lane & 3) * 2;

    // stage L1 chunk0 early
    stageW<256, WS1, PL1>(g_W1h, g_W1l, 0, wst, tid); CP_COMMIT;

    // padded input row
    for (int i = tid; i < 320; i += 256) {
        float v = 0.f;
        if (i >= 2 && i < 302) v = x[b * NFX + i - 2];
        s_xp[i] = v;
    }
    __syncthreads();

    // ---- build A (fp16, single plane) [64 x 288] ----
    for (int e = tid; e < 64 * 288; e += 256) {
        int m = e / 288, k = e - m * 288;
        int p = pos0 + m, h = p / 19, w = p - h * 19;
        float val = 0.f;
        if (p < NP) {
            if (k < 256) {
                int i = k >> 4, j = k & 15;
                float u = s_xp[i * 19 + h], v = s_xp[j * 19 + w];
                val = __fdividef(v - u, u + v + EPS);
            } else if (k < 272) {
                val = s_xp[(k - 256) * 19 + h];
            } else {
                val = s_xp[(k - 272) * 19 + w];
            }
        }
        s_A[m * AP + k] = __float2half_rn(val);
    }
    // (run_gemm's first internal __syncthreads orders A writes before ldmatrix)

    // ================= layer 1: K=288 -> 256 =================
    {
        float acc[2][8][4] = {};
        run_gemm<9, 4, 256, WS1, PL1>(aBase, wst, g_W1h, g_W1l, acc, wm, wn, lane, tid);
        stageW<128, WS2, PL2>(g_W2h, g_W2l, 0, wst, tid); CP_COMMIT;  // pre-stage L2
        #pragma unroll
        for (int mf = 0; mf < 2; mf++) {
            int rb = wm * 32 + mf * 16 + r0;
            #pragma unroll
            for (int ng = 0; ng < 4; ng++)
                #pragma unroll
                for (int e = 0; e < 2; e++) {
                    int col = (wn * 4 + ng) * 16 + e * 8 + c0;
                    const float* a = acc[mf][ng * 2 + e];
                    float bb0 = __ldg(b1 + col), bb1 = __ldg(b1 + col + 1);
                    *(__half2*)(s_A + rb * AP + col) =
                        __floats2half2_rn(leaky(a[0] + bb0), leaky(a[1] + bb1));
                    *(__half2*)(s_A + (rb + 8) * AP + col) =
                        __floats2half2_rn(leaky(a[2] + bb0), leaky(a[3] + bb1));
                }
        }
    }
    __syncthreads();

    // ================= layer 2: K=256 -> 128 =================
    {
        float acc[2][4][4] = {};
        run_gemm<8, 2, 128, WS2, PL2>(aBase, wst, g_W2h, g_W2l, acc, wm, wn, lane, tid);
        stageW<64, WS3, PL3>(g_W3h, g_W3l, 0, wst, tid); CP_COMMIT;   // pre-stage L3
        #pragma unroll
        for (int mf = 0; mf < 2; mf++) {
            int rb = wm * 32 + mf * 16 + r0;
            #pragma unroll
            for (int ng = 0; ng < 2; ng++)
                #pragma unroll
                for (int e = 0; e < 2; e++) {
                    int col = (wn * 2 + ng) * 16 + e * 8 + c0;
                    const float* a = acc[mf][ng * 2 + e];
                    float bb0 = __ldg(b2 + col), bb1 = __ldg(b2 + col + 1);
                    #pragma unroll
                    for (int hf = 0; hf < 2; hf++) {
                        int row = rb + hf * 8, p = pos0 + row;
                        float v0 = leaky(a[hf * 2 + 0] + bb0);
                        float v1 = leaky(a[hf * 2 + 1] + bb1);
                        *(__half2*)(s_A + row * AP + col) = __floats2half2_rn(v0, v1);
                        if (p < NP)
                            *(float2*)(g_gbuf + ((size_t)b * NP + p) * 128 + col) = make_float2(v0, v1);
                    }
                }
        }
    }
    __syncthreads();

    // ================= layer 3: K=128 -> 64 =================
    {
        float acc[2][2][4] = {};
        run_gemm<4, 1, 64, WS3, PL3>(aBase, wst, g_W3h, g_W3l, acc, wm, wn, lane, tid);
        #pragma unroll
        for (int mf = 0; mf < 2; mf++) {
            int rb = wm * 32 + mf * 16 + r0;
            #pragma unroll
            for (int e = 0; e < 2; e++) {
                int col = wn * 16 + e * 8 + c0;
                const float* a = acc[mf][e];
                float bb0 = __ldg(b3 + col), bb1 = __ldg(b3 + col + 1);
                *(float2*)(s_h3 + rb * 68 + col) = make_float2(relu(a[0] + bb0), relu(a[1] + bb1));
                *(float2*)(s_h3 + (rb + 8) * 68 + col) = make_float2(relu(a[2] + bb0), relu(a[3] + bb1));
            }
        }
    }
    __syncthreads();

    // ================= layer 4: 64 -> 4, logits =================
    {
        int m = tid >> 2, oh = tid & 3;
        int p = pos0 + m;
        float acc = __ldg(b4 + oh);
        const float* h3 = s_h3 + m * 68;
        #pragma unroll 16
        for (int c = 0; c < 64; c++) acc += h3[c] * __ldg(g_w4t + c * 4 + oh);
        if (p < NP) g_mbuf[((size_t)b * NP + p) * 4 + oh] = relu(acc);
    }
}

// ---------------- softmax over 361 positions + weighted reduction ----------------
__global__ __launch_bounds__(128) void softmax_kernel(float* __restrict__ out) {
    __shared__ float s_m[NP * 4];
    __shared__ float s_w[NP * 4];
    __shared__ float s_mx[4];
    __shared__ float s_iz[4];
    const int b = blockIdx.x;
    const int tid = threadIdx.x;

    for (int i = tid; i < NP * 4; i += 128) s_m[i] = g_mbuf[b * NP * 4 + i];
    __syncthreads();
    if (tid < 4) {
        float mx = -1e30f;
        for (int p = 0; p < NP; p++) mx = fmaxf(mx, s_m[p * 4 + tid]);
        s_mx[tid] = mx;
    }
    __syncthreads();
    for (int i = tid; i < NP * 4; i += 128) s_w[i] = __expf(s_m[i] - s_mx[i & 3]);
    __syncthreads();
    if (tid < 4) {
        float z = 0.f;
        for (int p = 0; p < NP; p++) z += s_w[p * 4 + tid];
        s_iz[tid] = __fdividef(1.f, z);
    }
    __syncthreads();
    const int head = tid >> 5;
    const float* gp = g_gbuf + (size_t)b * NP * 128 + tid;
    float acc = 0.f;
    #pragma unroll 4
    for (int p = 0; p < NP; p++) acc += s_w[p * 4 + head] * gp[(size_t)p * 128];
    out[b * 128 + tid] = acc * s_iz[head];
}

// ---------------- launch ----------------
extern "C" void kernel_launch(void* const* d_in, const int* in_sizes, int n_in,
                              void* d_out, int out_size) {
    const float* x  = (const float*)d_in[0];
    const float* w1 = (const float*)d_in[1];
    const float* b1 = (const float*)d_in[2];
    const float* w2 = (const float*)d_in[3];
    const float* b2 = (const float*)d_in[4];
    const float* w3 = (const float*)d_in[5];
    const float* b3 = (const float*)d_in[6];
    const float* w4 = (const float*)d_in[7];
    const float* b4 = (const float*)d_in[8];
    float* out = (float*)d_out;

    cudaFuncSetAttribute(mlp_kernel, cudaFuncAttributeMaxDynamicSharedMemorySize, SMEM_TOTAL);

    prep_kernel<<<128, 256>>>(w1, w2, w3, w4);
    mlp_kernel<<<dim3(NB, 6), 256, SMEM_TOTAL>>>(x, b1, b2, b3, b4);
    softmax_kernel<<<NB, 128>>>(out);
}

// round 10
// speedup vs baseline: 4.6004x; 1.3612x over previous
#include <cuda_runtime.h>
#include <cuda_fp16.h>
#include <cstdint>

#define EPS 1e-5f
#define NB 512
#define NFX 300
#define NP 361
#define AP 296              // A-plane row stride (halfs)

// per-layer staging strides (halfs) and plane sizes (bytes), k32 chunks, single plane
#define WS1 264
#define WS2 136
#define WS3 72
#define PL1 (32 * WS1 * 2)  // 16896
#define PL2 (32 * WS2 * 2)  // 8704
#define PL3 (32 * WS3 * 2)  // 4608

#define A_OFF 1280                       // after 320-float xp
#define W_OFF (A_OFF + 64 * AP * 2)      // 39168
#define SMEM_TOTAL (W_OFF + 2 * PL1)     // 72960  -> 2 CTAs/SM

// ---------------- static device scratch ----------------
__device__ __align__(16) __half g_W1[288 * 256];   // [k][o]
__device__ __align__(16) __half g_W2[256 * 128];
__device__ __align__(16) __half g_W3[128 * 64];
__device__ float g_w4t[256];
__device__ float g_gbuf[(size_t)NB * NP * 128];
__device__ float g_mbuf[NB * NP * 4];

// ---------------- helpers ----------------
__device__ __forceinline__ uint32_t cvta_s(const void* p) {
    uint32_t a; asm("{.reg .u64 t; cvta.to.shared.u64 t,%1; cvt.u32.u64 %0,t;}" : "=r"(a) : "l"(p)); return a;
}
__device__ __forceinline__ void ldmA(uint32_t a, uint32_t r[4]) {
    asm volatile("ldmatrix.sync.aligned.m8n8.x4.shared.b16 {%0,%1,%2,%3},[%4];"
                 : "=r"(r[0]), "=r"(r[1]), "=r"(r[2]), "=r"(r[3]) : "r"(a));
}
__device__ __forceinline__ void ldmBT(uint32_t a, uint32_t r[4]) {
    asm volatile("ldmatrix.sync.aligned.m8n8.x4.trans.shared.b16 {%0,%1,%2,%3},[%4];"
                 : "=r"(r[0]), "=r"(r[1]), "=r"(r[2]), "=r"(r[3]) : "r"(a));
}
__device__ __forceinline__ void mma(float c[4], const uint32_t a[4], uint32_t b0, uint32_t b1) {
    asm volatile("mma.sync.aligned.m16n8k16.row.col.f32.f16.f16.f32 "
                 "{%0,%1,%2,%3},{%4,%5,%6,%7},{%8,%9},{%0,%1,%2,%3};"
                 : "+f"(c[0]), "+f"(c[1]), "+f"(c[2]), "+f"(c[3])
                 : "r"(a[0]), "r"(a[1]), "r"(a[2]), "r"(a[3]), "r"(b0), "r"(b1));
}
__device__ __forceinline__ void cpa16(uint32_t d, const void* s) {
    asm volatile("cp.async.ca.shared.global [%0],[%1],16;" :: "r"(d), "l"(s));
}
#define CP_COMMIT asm volatile("cp.async.commit_group;")
#define CP_WAIT1  asm volatile("cp.async.wait_group 1;")
#define CP_WAIT0  asm volatile("cp.async.wait_group 0;")

__device__ __forceinline__ float leaky(float v) { return v >= 0.f ? v : 0.01f * v; }
__device__ __forceinline__ float relu(float v)  { return v > 0.f ? v : 0.f; }

// stage one k32 chunk of a [K][N] fp16 weight matrix
template<int N, int WSN>
__device__ __forceinline__ void stageW(const __half* gw, int chunk, uint32_t dst, int tid) {
    const int ROWU = N / 8;            // 16B units per row
    const int TOT = 32 * ROWU;
    for (int u = tid; u < TOT; u += 256) {
        int r = u / ROWU, s = u - r * ROWU;
        cpa16(dst + (r * WSN + s * 8) * 2, gw + (size_t)(chunk * 32 + r) * N + s * 8);
    }
}

// 1-term fp16 GEMM: D = A * B. A: fp16 plane [64 x K] (stride AP), B staged from global.
// Caller must have staged+committed chunk 0 into buffer 0.
template<int CH, int NFRG, int N, int WSN, int PL>
__device__ __forceinline__ void run_gemm(uint32_t aBase, uint32_t wst, const __half* gW,
                                         float (&acc)[2][NFRG * 2][4],
                                         int wm, int wn, int lane, int tid) {
    const uint32_t aoff = (uint32_t)(((wm * 32 + (lane & 15)) * AP + (lane >> 4) * 8) * 2);
    const int bg = lane >> 3, bi = lane & 7;
    const uint32_t boff = (uint32_t)((((bg & 1) * 8 + bi) * WSN + (bg >> 1) * 8) * 2);
    for (int c = 0; c < CH; c++) {
        if (c + 1 < CH) {
            stageW<N, WSN>(gW, c + 1, wst + ((c + 1) & 1) * PL, tid);
            CP_COMMIT; CP_WAIT1;
        } else {
            CP_WAIT0;
        }
        __syncthreads();
        const uint32_t wb = wst + (c & 1) * PL;
        #pragma unroll
        for (int ks = 0; ks < 2; ks++) {
            uint32_t ab = aBase + aoff + (uint32_t)(c * 2 + ks) * 32;
            uint32_t a0[4], a1[4];
            ldmA(ab, a0);
            ldmA(ab + 16 * AP * 2, a1);
            const uint32_t kb = wb + boff + (uint32_t)ks * 16 * WSN * 2;
            #pragma unroll
            for (int ng = 0; ng < NFRG; ng++) {
                uint32_t nb = (uint32_t)(((wn * NFRG + ng) * 16) * 2);
                uint32_t bh[4];
                ldmBT(kb + nb, bh);
                mma(acc[0][ng * 2 + 0], a0, bh[0], bh[1]);
                mma(acc[0][ng * 2 + 1], a0, bh[2], bh[3]);
                mma(acc[1][ng * 2 + 0], a1, bh[0], bh[1]);
                mma(acc[1][ng * 2 + 1], a1, bh[2], bh[3]);
            }
        }
        __syncthreads();
    }
}

// ---------------- prep: repack weights to fp16 [k][o] ----------------
__global__ void prep_kernel(const float* __restrict__ w1, const float* __restrict__ w2,
                            const float* __restrict__ w3, const float* __restrict__ w4) {
    int idx = blockIdx.x * blockDim.x + threadIdx.x;
    int stride = gridDim.x * blockDim.x;
    // layer 1 combined K=288: k<256 NDI weight (i=k>>4,j=k&15); 256..271: -wr[i]; 272..287: +wc[j]
    for (int t = idx; t < 288 * 256; t += stride) {
        int k = t >> 8, o = t & 255;
        float v;
        if (k < 256) {
            int i = k >> 4, j = k & 15;
            v = w1[o * 512 + i * 32 + j * 2 + 1];
        } else if (k < 272) {
            int i = k - 256; float s = 0.f;
            #pragma unroll
            for (int j = 0; j < 16; j++) s += w1[o * 512 + i * 32 + j * 2];
            v = -s;
        } else {
            int j = k - 272; float s = 0.f;
            #pragma unroll
            for (int i = 0; i < 16; i++) s += w1[o * 512 + i * 32 + j * 2];
            v = s;
        }
        g_W1[t] = __float2half_rn(v);
    }
    for (int t = idx; t < 256 * 128; t += stride) {
        int k = t >> 7, o = t & 127;
        g_W2[t] = __float2half_rn(w2[o * 256 + k]);
    }
    for (int t = idx; t < 128 * 64; t += stride) {
        int k = t >> 6, o = t & 63;
        g_W3[t] = __float2half_rn(w3[o * 128 + k]);
    }
    for (int t = idx; t < 256; t += stride) g_w4t[t] = w4[(t & 3) * 64 + (t >> 2)];
}

// ---------------- main fused kernel: one CTA per (batch, 64-pos tile), 2 CTA/SM ----------------
__global__ __launch_bounds__(256, 2) void mlp_kernel(const float* __restrict__ x,
                                                     const float* __restrict__ b1,
                                                     const float* __restrict__ b2,
                                                     const float* __restrict__ b3,
                                                     const float* __restrict__ b4) {
    extern __shared__ char smem[];
    float* s_xp = (float*)smem;
    __half* s_A = (__half*)(smem + A_OFF);
    float* s_h3 = (float*)(smem + W_OFF);    // reuses staging area after L3 GEMM
    const uint32_t sb = cvta_s(smem);
    const uint32_t aBase = sb + A_OFF, wst = sb + W_OFF;

    const int b = blockIdx.x, pos0 = blockIdx.y * 64, tid = threadIdx.x;
    const int lane = tid & 31, ww = tid >> 5;
    const int wm = ww >> 2, wn = ww & 3;     // 2 m-warps x 4 n-warps
    const int r0 = lane >> 2, c0 = (lane & 3) * 2;

    // stage L1 chunk0 early
    stageW<256, WS1>(g_W1, 0, wst, tid); CP_COMMIT;

    // padded input row
    for (int i = tid; i < 320; i += 256) {
        float v = 0.f;
        if (i >= 2 && i < 302) v = x[b * NFX + i - 2];
        s_xp[i] = v;
    }
    __syncthreads();

    // ---- build A (fp16) [64 x 288] ----
    for (int e = tid; e < 64 * 288; e += 256) {
        int m = e / 288, k = e - m * 288;
        int p = pos0 + m, h = p / 19, w = p - h * 19;
        float val = 0.f;
        if (p < NP) {
            if (k < 256) {
                int i = k >> 4, j = k & 15;
                float u = s_xp[i * 19 + h], v = s_xp[j * 19 + w];
                val = __fdividef(v - u, u + v + EPS);
            } else if (k < 272) {
                val = s_xp[(k - 256) * 19 + h];
            } else {
                val = s_xp[(k - 272) * 19 + w];
            }
        }
        s_A[m * AP + k] = __float2half_rn(val);
    }
    // (run_gemm's first internal __syncthreads orders A writes before ldmatrix)

    // ================= layer 1: K=288 -> 256 =================
    {
        float acc[2][8][4] = {};
        run_gemm<9, 4, 256, WS1, PL1>(aBase, wst, g_W1, acc, wm, wn, lane, tid);
        stageW<128, WS2>(g_W2, 0, wst, tid); CP_COMMIT;  // pre-stage L2
        #pragma unroll
        for (int mf = 0; mf < 2; mf++) {
            int rb = wm * 32 + mf * 16 + r0;
            #pragma unroll
            for (int ng = 0; ng < 4; ng++)
                #pragma unroll
                for (int e = 0; e < 2; e++) {
                    int col = (wn * 4 + ng) * 16 + e * 8 + c0;
                    const float* a = acc[mf][ng * 2 + e];
                    float bb0 = __ldg(b1 + col), bb1 = __ldg(b1 + col + 1);
                    *(__half2*)(s_A + rb * AP + col) =
                        __floats2half2_rn(leaky(a[0] + bb0), leaky(a[1] + bb1));
                    *(__half2*)(s_A + (rb + 8) * AP + col) =
                        __floats2half2_rn(leaky(a[2] + bb0), leaky(a[3] + bb1));
                }
        }
    }
    __syncthreads();

    // ================= layer 2: K=256 -> 128 =================
    {
        float acc[2][4][4] = {};
        run_gemm<8, 2, 128, WS2, PL2>(aBase, wst, g_W2, acc, wm, wn, lane, tid);
        stageW<64, WS3>(g_W3, 0, wst, tid); CP_COMMIT;   // pre-stage L3
        #pragma unroll
        for (int mf = 0; mf < 2; mf++) {
            int rb = wm * 32 + mf * 16 + r0;
            #pragma unroll
            for (int ng = 0; ng < 2; ng++)
                #pragma unroll
                for (int e = 0; e < 2; e++) {
                    int col = (wn * 2 + ng) * 16 + e * 8 + c0;
                    const float* a = acc[mf][ng * 2 + e];
                    float bb0 = __ldg(b2 + col), bb1 = __ldg(b2 + col + 1);
                    #pragma unroll
                    for (int hf = 0; hf < 2; hf++) {
                        int row = rb + hf * 8, p = pos0 + row;
                        float v0 = leaky(a[hf * 2 + 0] + bb0);
                        float v1 = leaky(a[hf * 2 + 1] + bb1);
                        *(__half2*)(s_A + row * AP + col) = __floats2half2_rn(v0, v1);
                        if (p < NP)
                            *(float2*)(g_gbuf + ((size_t)b * NP + p) * 128 + col) = make_float2(v0, v1);
                    }
                }
        }
    }
    __syncthreads();

    // ================= layer 3: K=128 -> 64 =================
    {
        float acc[2][2][4] = {};
        run_gemm<4, 1, 64, WS3, PL3>(aBase, wst, g_W3, acc, wm, wn, lane, tid);
        #pragma unroll
        for (int mf = 0; mf < 2; mf++) {
            int rb = wm * 32 + mf * 16 + r0;
            #pragma unroll
            for (int e = 0; e < 2; e++) {
                int col = wn * 16 + e * 8 + c0;
                const float* a = acc[mf][e];
                float bb0 = __ldg(b3 + col), bb1 = __ldg(b3 + col + 1);
                *(float2*)(s_h3 + rb * 68 + col) = make_float2(relu(a[0] + bb0), relu(a[1] + bb1));
                *(float2*)(s_h3 + (rb + 8) * 68 + col) = make_float2(relu(a[2] + bb0), relu(a[3] + bb1));
            }
        }
    }
    __syncthreads();

    // ================= layer 4: 64 -> 4, logits =================
    {
        int m = tid >> 2, oh = tid & 3;
        int p = pos0 + m;
        float acc = __ldg(b4 + oh);
        const float* h3 = s_h3 + m * 68;
        #pragma unroll 16
        for (int c = 0; c < 64; c++) acc += h3[c] * __ldg(g_w4t + c * 4 + oh);
        if (p < NP) g_mbuf[((size_t)b * NP + p) * 4 + oh] = relu(acc);
    }
}

// ---------------- softmax over 361 positions + weighted reduction ----------------
__global__ __launch_bounds__(128) void softmax_kernel(float* __restrict__ out) {
    __shared__ float s_m[NP * 4];
    __shared__ float s_w[NP * 4];
    __shared__ float s_mx[4];
    __shared__ float s_iz[4];
    const int b = blockIdx.x;
    const int tid = threadIdx.x;

    for (int i = tid; i < NP * 4; i += 128) s_m[i] = g_mbuf[b * NP * 4 + i];
    __syncthreads();
    if (tid < 4) {
        float mx = -1e30f;
        for (int p = 0; p < NP; p++) mx = fmaxf(mx, s_m[p * 4 + tid]);
        s_mx[tid] = mx;
    }
    __syncthreads();
    for (int i = tid; i < NP * 4; i += 128) s_w[i] = __expf(s_m[i] - s_mx[i & 3]);
    __syncthreads();
    if (tid < 4) {
        float z = 0.f;
        for (int p = 0; p < NP; p++) z += s_w[p * 4 + tid];
        s_iz[tid] = __fdividef(1.f, z);
    }
    __syncthreads();
    const int head = tid >> 5;
    const float* gp = g_gbuf + (size_t)b * NP * 128 + tid;
    float acc = 0.f;
    #pragma unroll 4
    for (int p = 0; p < NP; p++) acc += s_w[p * 4 + head] * gp[(size_t)p * 128];
    out[b * 128 + tid] = acc * s_iz[head];
}

// ---------------- launch ----------------
extern "C" void kernel_launch(void* const* d_in, const int* in_sizes, int n_in,
                              void* d_out, int out_size) {
    const float* x  = (const float*)d_in[0];
    const float* w1 = (const float*)d_in[1];
    const float* b1 = (const float*)d_in[2];
    const float* w2 = (const float*)d_in[3];
    const float* b2 = (const float*)d_in[4];
    const float* w3 = (const float*)d_in[5];
    const float* b3 = (const float*)d_in[6];
    const float* w4 = (const float*)d_in[7];
    const float* b4 = (const float*)d_in[8];
    float* out = (float*)d_out;

    cudaFuncSetAttribute(mlp_kernel, cudaFuncAttributeMaxDynamicSharedMemorySize, SMEM_TOTAL);

    prep_kernel<<<128, 256>>>(w1, w2, w3, w4);
    mlp_kernel<<<dim3(NB, 6), 256, SMEM_TOTAL>>>(x, b1, b2, b3, b4);
    softmax_kernel<<<NB, 128>>>(out);
}

// round 11
// speedup vs baseline: 5.5699x; 1.2107x over previous
#include <cuda_runtime.h>
#include <cuda_fp16.h>
#include <cstdint>

#define EPS 1e-5f
#define NB 512
#define NFX 300
#define NP 361
#define AP 296              // A-plane row stride (halfs)

// per-layer staging strides (halfs) and plane sizes (bytes), k32 chunks
#define WS1 264
#define WS2 136
#define WS3 72
#define PL1 (32 * WS1 * 2)  // 16896
#define PL2 (32 * WS2 * 2)  // 8704
#define PL3 (32 * WS3 * 2)  // 4608

#define A_OFF 1280                       // after 320-float xp (+ s_e reuse)
#define W_OFF (A_OFF + 64 * AP * 2)      // 39168
#define SMEM_TOTAL (W_OFF + 2 * PL1)     // 72960  -> 2 CTAs/SM

// ---------------- static device scratch ----------------
__device__ __align__(16) __half g_W1[288 * 256];   // [k][o]
__device__ __align__(16) __half g_W2[256 * 128];
__device__ __align__(16) __half g_W3[128 * 64];
__device__ float g_w4t[256];
__device__ float g_acc[NB * 132];        // per-batch: [0..127] num, [128..131] den

// ---------------- helpers ----------------
__device__ __forceinline__ uint32_t cvta_s(const void* p) {
    uint32_t a; asm("{.reg .u64 t; cvta.to.shared.u64 t,%1; cvt.u32.u64 %0,t;}" : "=r"(a) : "l"(p)); return a;
}
__device__ __forceinline__ void ldmA(uint32_t a, uint32_t r[4]) {
    asm volatile("ldmatrix.sync.aligned.m8n8.x4.shared.b16 {%0,%1,%2,%3},[%4];"
                 : "=r"(r[0]), "=r"(r[1]), "=r"(r[2]), "=r"(r[3]) : "r"(a));
}
__device__ __forceinline__ void ldmBT(uint32_t a, uint32_t r[4]) {
    asm volatile("ldmatrix.sync.aligned.m8n8.x4.trans.shared.b16 {%0,%1,%2,%3},[%4];"
                 : "=r"(r[0]), "=r"(r[1]), "=r"(r[2]), "=r"(r[3]) : "r"(a));
}
__device__ __forceinline__ void mma(float c[4], const uint32_t a[4], uint32_t b0, uint32_t b1) {
    asm volatile("mma.sync.aligned.m16n8k16.row.col.f32.f16.f16.f32 "
                 "{%0,%1,%2,%3},{%4,%5,%6,%7},{%8,%9},{%0,%1,%2,%3};"
                 : "+f"(c[0]), "+f"(c[1]), "+f"(c[2]), "+f"(c[3])
                 : "r"(a[0]), "r"(a[1]), "r"(a[2]), "r"(a[3]), "r"(b0), "r"(b1));
}
__device__ __forceinline__ void cpa16(uint32_t d, const void* s) {
    asm volatile("cp.async.ca.shared.global [%0],[%1],16;" :: "r"(d), "l"(s));
}
#define CP_COMMIT asm volatile("cp.async.commit_group;")
#define CP_WAIT0  asm volatile("cp.async.wait_group 0;")

__device__ __forceinline__ float leaky(float v) { return v >= 0.f ? v : 0.01f * v; }
__device__ __forceinline__ float relu(float v)  { return v > 0.f ? v : 0.f; }

// stage one k32 chunk of a [K][N] fp16 weight matrix
template<int N, int WSN>
__device__ __forceinline__ void stageW(const __half* gw, int chunk, uint32_t dst, int tid) {
    const int ROWU = N / 8;
    const int TOT = 32 * ROWU;
    for (int u = tid; u < TOT; u += 256) {
        int r = u / ROWU, s = u - r * ROWU;
        cpa16(dst + (r * WSN + s * 8) * 2, gw + (size_t)(chunk * 32 + r) * N + s * 8);
    }
}

// 1-term fp16 GEMM: D = A * B. One __syncthreads per chunk:
//   wait(chunk c) -> sync -> stage(c+1) -> compute(c).  Trailing sync before return.
// Caller must have staged+committed chunk 0 into buffer 0.
template<int CH, int NFRG, int N, int WSN, int PL>
__device__ __forceinline__ void run_gemm(uint32_t aBase, uint32_t wst, const __half* gW,
                                         float (&acc)[2][NFRG * 2][4],
                                         int wm, int wn, int lane, int tid) {
    const uint32_t aoff = (uint32_t)(((wm * 32 + (lane & 15)) * AP + (lane >> 4) * 8) * 2);
    const int bg = lane >> 3, bi = lane & 7;
    const uint32_t boff = (uint32_t)((((bg & 1) * 8 + bi) * WSN + (bg >> 1) * 8) * 2);
    for (int c = 0; c < CH; c++) {
        CP_WAIT0;
        __syncthreads();               // chunk c visible; buffer (c+1)&1 free
        if (c + 1 < CH) {
            stageW<N, WSN>(gW, c + 1, wst + ((c + 1) & 1) * PL, tid);
            CP_COMMIT;
        }
        const uint32_t wb = wst + (c & 1) * PL;
        #pragma unroll
        for (int ks = 0; ks < 2; ks++) {
            uint32_t ab = aBase + aoff + (uint32_t)(c * 2 + ks) * 32;
            uint32_t a0[4], a1[4];
            ldmA(ab, a0);
            ldmA(ab + 16 * AP * 2, a1);
            const uint32_t kb = wb + boff + (uint32_t)ks * 16 * WSN * 2;
            #pragma unroll
            for (int ng = 0; ng < NFRG; ng++) {
                uint32_t nb = (uint32_t)(((wn * NFRG + ng) * 16) * 2);
                uint32_t bh[4];
                ldmBT(kb + nb, bh);
                mma(acc[0][ng * 2 + 0], a0, bh[0], bh[1]);
                mma(acc[0][ng * 2 + 1], a0, bh[2], bh[3]);
                mma(acc[1][ng * 2 + 0], a1, bh[0], bh[1]);
                mma(acc[1][ng * 2 + 1], a1, bh[2], bh[3]);
            }
        }
        __syncthreads();               // release read buffer before next stage overwrites / epilogue writes A
    }
}

// ---------------- prep: repack weights to fp16 [k][o] ----------------
__global__ void prep_kernel(const float* __restrict__ w1, const float* __restrict__ w2,
                            const float* __restrict__ w3, const float* __restrict__ w4) {
    int idx = blockIdx.x * blockDim.x + threadIdx.x;
    int stride = gridDim.x * blockDim.x;
    // layer 1 combined K=288: k<256 NDI weight (i=k>>4,j=k&15); 256..271: -wr[i]; 272..287: +wc[j]
    for (int t = idx; t < 288 * 256; t += stride) {
        int k = t >> 8, o = t & 255;
        float v;
        if (k < 256) {
            int i = k >> 4, j = k & 15;
            v = w1[o * 512 + i * 32 + j * 2 + 1];
        } else if (k < 272) {
            int i = k - 256; float s = 0.f;
            #pragma unroll
            for (int j = 0; j < 16; j++) s += w1[o * 512 + i * 32 + j * 2];
            v = -s;
        } else {
            int j = k - 272; float s = 0.f;
            #pragma unroll
            for (int i = 0; i < 16; i++) s += w1[o * 512 + i * 32 + j * 2];
            v = s;
        }
        g_W1[t] = __float2half_rn(v);
    }
    for (int t = idx; t < 256 * 128; t += stride) {
        int k = t >> 7, o = t & 127;
        g_W2[t] = __float2half_rn(w2[o * 256 + k]);
    }
    for (int t = idx; t < 128 * 64; t += stride) {
        int k = t >> 6, o = t & 63;
        g_W3[t] = __float2half_rn(w3[o * 128 + k]);
    }
    for (int t = idx; t < 256; t += stride) g_w4t[t] = w4[(t & 3) * 64 + (t >> 2)];
}

// ---------------- zero accumulators (graph-replay safe) ----------------
__global__ void zero_kernel() {
    int i = blockIdx.x * blockDim.x + threadIdx.x;
    if (i < NB * 132) g_acc[i] = 0.f;
}

// ---------------- main fused kernel: one CTA per (batch, 64-pos tile), 2 CTA/SM ----------------
__global__ __launch_bounds__(256, 2) void mlp_kernel(const float* __restrict__ x,
                                                     const float* __restrict__ b1,
                                                     const float* __restrict__ b2,
                                                     const float* __restrict__ b3,
                                                     const float* __restrict__ b4) {
    extern __shared__ char smem[];
    float* s_xp = (float*)smem;              // 320 floats; reused as s_e later
    float* s_e  = (float*)smem;              // 256 floats (exp weights), after xp is dead
    __half* s_A = (__half*)(smem + A_OFF);
    float* s_h3 = (float*)(smem + W_OFF);    // staging area reuse after L3 GEMM
    float* s_part = (float*)(smem + W_OFF + 20480);  // 256 floats partial sums
    const uint32_t sb = cvta_s(smem);
    const uint32_t aBase = sb + A_OFF, wst = sb + W_OFF;

    const int b = blockIdx.x, pos0 = blockIdx.y * 64, tid = threadIdx.x;
    const int lane = tid & 31, ww = tid >> 5;
    const int wm = ww >> 2, wn = ww & 3;     // 2 m-warps x 4 n-warps
    const int r0 = lane >> 2, c0 = (lane & 3) * 2;

    // stage L1 chunk0 early
    stageW<256, WS1>(g_W1, 0, wst, tid); CP_COMMIT;

    // padded input row
    for (int i = tid; i < 320; i += 256) {
        float v = 0.f;
        if (i >= 2 && i < 302) v = x[b * NFX + i - 2];
        s_xp[i] = v;
    }
    __syncthreads();

    // ---- build A (fp16) [64 x 288] ----
    for (int e = tid; e < 64 * 288; e += 256) {
        int m = e / 288, k = e - m * 288;
        int p = pos0 + m, h = p / 19, w = p - h * 19;
        float val = 0.f;
        if (p < NP) {
            if (k < 256) {
                int i = k >> 4, j = k & 15;
                float u = s_xp[i * 19 + h], v = s_xp[j * 19 + w];
                val = __fdividef(v - u, u + v + EPS);
            } else if (k < 272) {
                val = s_xp[(k - 256) * 19 + h];
            } else {
                val = s_xp[(k - 272) * 19 + w];
            }
        }
        s_A[m * AP + k] = __float2half_rn(val);
    }

    // ================= layer 1: K=288 -> 256 =================
    {
        float acc[2][8][4] = {};
        run_gemm<9, 4, 256, WS1, PL1>(aBase, wst, g_W1, acc, wm, wn, lane, tid);
        stageW<128, WS2>(g_W2, 0, wst, tid); CP_COMMIT;  // pre-stage L2
        #pragma unroll
        for (int mf = 0; mf < 2; mf++) {
            int rb = wm * 32 + mf * 16 + r0;
            #pragma unroll
            for (int ng = 0; ng < 4; ng++)
                #pragma unroll
                for (int e = 0; e < 2; e++) {
                    int col = (wn * 4 + ng) * 16 + e * 8 + c0;
                    const float* a = acc[mf][ng * 2 + e];
                    float bb0 = __ldg(b1 + col), bb1 = __ldg(b1 + col + 1);
                    *(__half2*)(s_A + rb * AP + col) =
                        __floats2half2_rn(leaky(a[0] + bb0), leaky(a[1] + bb1));
                    *(__half2*)(s_A + (rb + 8) * AP + col) =
                        __floats2half2_rn(leaky(a[2] + bb0), leaky(a[3] + bb1));
                }
        }
    }
    __syncthreads();

    // ================= layer 2: K=256 -> 128 =================
    {
        float acc[2][4][4] = {};
        run_gemm<8, 2, 128, WS2, PL2>(aBase, wst, g_W2, acc, wm, wn, lane, tid);
        stageW<64, WS3>(g_W3, 0, wst, tid); CP_COMMIT;   // pre-stage L3
        #pragma unroll
        for (int mf = 0; mf < 2; mf++) {
            int rb = wm * 32 + mf * 16 + r0;
            #pragma unroll
            for (int ng = 0; ng < 2; ng++)
                #pragma unroll
                for (int e = 0; e < 2; e++) {
                    int col = (wn * 2 + ng) * 16 + e * 8 + c0;
                    const float* a = acc[mf][ng * 2 + e];
                    float bb0 = __ldg(b2 + col), bb1 = __ldg(b2 + col + 1);
                    #pragma unroll
                    for (int hf = 0; hf < 2; hf++) {
                        int row = rb + hf * 8;
                        *(__half2*)(s_A + row * AP + col) =
                            __floats2half2_rn(leaky(a[hf * 2 + 0] + bb0), leaky(a[hf * 2 + 1] + bb1));
                    }
                }
        }
    }
    __syncthreads();

    // ================= layer 3: K=128 -> 64 =================
    {
        float acc[2][2][4] = {};
        run_gemm<4, 1, 64, WS3, PL3>(aBase, wst, g_W3, acc, wm, wn, lane, tid);
        #pragma unroll
        for (int mf = 0; mf < 2; mf++) {
            int rb = wm * 32 + mf * 16 + r0;
            #pragma unroll
            for (int e = 0; e < 2; e++) {
                int col = wn * 16 + e * 8 + c0;
                const float* a = acc[mf][e];
                float bb0 = __ldg(b3 + col), bb1 = __ldg(b3 + col + 1);
                *(float2*)(s_h3 + rb * 68 + col) = make_float2(relu(a[0] + bb0), relu(a[1] + bb1));
                *(float2*)(s_h3 + (rb + 8) * 68 + col) = make_float2(relu(a[2] + bb0), relu(a[3] + bb1));
            }
        }
    }
    __syncthreads();

    // ================= layer 4: logits -> unnormalized exp weights =================
    {
        int m = tid >> 2, oh = tid & 3;      // 256 threads cover 64 rows x 4 heads
        float acc = __ldg(b4 + oh);
        const float* h3 = s_h3 + m * 68;
        #pragma unroll 16
        for (int c = 0; c < 64; c++) acc += h3[c] * __ldg(g_w4t + c * 4 + oh);
        float ev = __expf(relu(acc));
        if (pos0 + m >= NP) ev = 0.f;        // padding rows contribute nothing
        s_e[m * 4 + oh] = ev;
    }
    __syncthreads();

    // ================= fused softmax partials: num[c], den[head] =================
    {
        int c = tid & 127, half = tid >> 7;  // 2 m-halves per channel
        int head = c >> 5;
        float sum = 0.f;
        #pragma unroll 8
        for (int m = half * 32; m < half * 32 + 32; m++)
            sum += s_e[m * 4 + head] * __half2float(s_A[m * AP + c]);
        s_part[half * 128 + c] = sum;
    }
    __syncthreads();
    if (tid < 128) atomicAdd(&g_acc[b * 132 + tid], s_part[tid] + s_part[128 + tid]);
    if (tid < 4) {
        float d = 0.f;
        #pragma unroll 16
        for (int m = 0; m < 64; m++) d += s_e[m * 4 + tid];
        atomicAdd(&g_acc[b * 132 + 128 + tid], d);
    }
}

// ---------------- final divide ----------------
__global__ __launch_bounds__(128) void final_kernel(float* __restrict__ out) {
    int b = blockIdx.x, c = threadIdx.x;
    out[b * 128 + c] = g_acc[b * 132 + c] / g_acc[b * 132 + 128 + (c >> 5)];
}

// ---------------- launch ----------------
extern "C" void kernel_launch(void* const* d_in, const int* in_sizes, int n_in,
                              void* d_out, int out_size) {
    const float* x  = (const float*)d_in[0];
    const float* w1 = (const float*)d_in[1];
    const float* b1 = (const float*)d_in[2];
    const float* w2 = (const float*)d_in[3];
    const float* b2 = (const float*)d_in[4];
    const float* w3 = (const float*)d_in[5];
    const float* b3 = (const float*)d_in[6];
    const float* w4 = (const float*)d_in[7];
    const float* b4 = (const float*)d_in[8];
    float* out = (float*)d_out;

    cudaFuncSetAttribute(mlp_kernel, cudaFuncAttributeMaxDynamicSharedMemorySize, SMEM_TOTAL);

    prep_kernel<<<128, 256>>>(w1, w2, w3, w4);
    zero_kernel<<<(NB * 132 + 255) / 256, 256>>>();
    mlp_kernel<<<dim3(NB, 6), 256, SMEM_TOTAL>>>(x, b1, b2, b3, b4);
    final_kernel<<<NB, 128>>>(out);
}